// round 1
// baseline (speedup 1.0000x reference)
#include <cuda_runtime.h>

// Scratch (no allocations allowed): per-block partial sums + final scalar.
#define NBLK_RED 1024
__device__ double g_partials[NBLK_RED];
__device__ float  g_total;

// ---------------------------------------------------------------------------
// Kernel 1: grid-stride float4 partial reduction. 1024 blocks x 256 threads.
// Each thread keeps 4 float lane-accumulators (64 adds each -> tiny error),
// combines to double, block tree-reduces in shared double, writes partial.
// ---------------------------------------------------------------------------
__global__ void __launch_bounds__(256) reduce_kernel(const float* __restrict__ x,
                                                     long long n4)
{
    const float4* __restrict__ x4 = (const float4*)x;
    long long idx    = (long long)blockIdx.x * blockDim.x + threadIdx.x;
    long long stride = (long long)gridDim.x * blockDim.x;

    float a0 = 0.f, a1 = 0.f, a2 = 0.f, a3 = 0.f;
    for (long long i = idx; i < n4; i += stride) {
        float4 v = x4[i];
        a0 += v.x; a1 += v.y; a2 += v.z; a3 += v.w;
    }
    double acc = (double)a0 + (double)a1 + (double)a2 + (double)a3;

    __shared__ double sdata[256];
    sdata[threadIdx.x] = acc;
    __syncthreads();
    for (int s = 128; s > 0; s >>= 1) {
        if (threadIdx.x < s) sdata[threadIdx.x] += sdata[threadIdx.x + s];
        __syncthreads();
    }
    if (threadIdx.x == 0) g_partials[blockIdx.x] = sdata[0];
}

// ---------------------------------------------------------------------------
// Kernel 2: single block folds 1024 partials -> s, computes the closed-form
// scalar: n = trunc(float(s)); total = n>1 ? n*(n-1)/2 : 0.
// ---------------------------------------------------------------------------
__global__ void __launch_bounds__(256) finalize_kernel()
{
    __shared__ double sdata[256];
    double acc = 0.0;
    for (int i = threadIdx.x; i < NBLK_RED; i += 256) acc += g_partials[i];
    sdata[threadIdx.x] = acc;
    __syncthreads();
    for (int s = 128; s > 0; s >>= 1) {
        if (threadIdx.x < s) sdata[threadIdx.x] += sdata[threadIdx.x + s];
        __syncthreads();
    }
    if (threadIdx.x == 0) {
        float  sf = (float)sdata[0];          // mimic jnp.sum's fp32 result
        double n  = trunc((double)sf);
        double total = (n > 1.0) ? n * (n - 1.0) * 0.5 : 0.0;
        g_total = (float)total;
    }
}

// ---------------------------------------------------------------------------
// Kernel 3: out = x + total, one float4 per thread (no loop).
// ---------------------------------------------------------------------------
__global__ void __launch_bounds__(256) add_kernel(const float* __restrict__ x,
                                                  float* __restrict__ out,
                                                  long long n4)
{
    long long i = (long long)blockIdx.x * blockDim.x + threadIdx.x;
    if (i >= n4) return;
    float t = g_total;                        // uniform load, L2-broadcast
    float4 v = ((const float4*)x)[i];
    v.x += t; v.y += t; v.z += t; v.w += t;
    ((float4*)out)[i] = v;
}

extern "C" void kernel_launch(void* const* d_in, const int* in_sizes, int n_in,
                              void* d_out, int out_size)
{
    const float* x  = (const float*)d_in[0];
    float*      out = (float*)d_out;
    long long n  = (long long)in_sizes[0];    // 8192*8192 = 67,108,864
    long long n4 = n >> 2;                    // divisible by 4

    reduce_kernel<<<NBLK_RED, 256>>>(x, n4);
    finalize_kernel<<<1, 256>>>();
    long long blocks = (n4 + 255) / 256;
    add_kernel<<<(unsigned)blocks, 256>>>(x, out, n4);
}